// round 16
// baseline (speedup 1.0000x reference)
#include <cuda_runtime.h>

typedef unsigned int   u32;
typedef unsigned short u16;

#define H 512
#define B 128
#define T 1024
#define NCLS 10
#define GRID 128
#define TPB 512

#define RSTRIDE 1040              // bytes per padded A/B smem row (520 halves)
#define SM_AHI 0                  // A hi : 32 rows
#define SM_ALO 33280              // A lo : 32 rows
#define SM_BHI 66560              // W hi : 64 rows
#define SM_BLO 133120             // W lo : 64 rows
#define SM_D   199680             // D: float[2][32][68] (k-slice partials)
#define SMEM_BYTES (199680 + 2*32*68*4)   // 217088

// ---------------- device scratch (static, no allocation) ----------------
__device__ uint4 g_hhi[2][B * H / 8];    // bf16 h hi, [b][k] rows
__device__ uint4 g_hlo[2][B * H / 8];    // bf16 h lo residual
__device__ float g_xT[T * B];            // transposed x [t][b]
__device__ unsigned g_cnt4[4];
__device__ unsigned g_gen4[4];

// ---------------- helpers ----------------
__device__ __forceinline__ u16 f2bf(float f) {
    u32 u = __float_as_uint(f);
    u32 r = (u + 0x7FFFu + ((u >> 16) & 1u)) >> 16;
    return (u16)r;
}
__device__ __forceinline__ float bf2f(u16 s) {
    return __uint_as_float(((u32)s) << 16);
}
__device__ __forceinline__ float sigf(float x) {
    return __fdividef(1.0f, 1.0f + __expf(-x));
}
__device__ __forceinline__ float tanf_(float x) {
    return __fdividef(2.0f, 1.0f + __expf(-2.0f * x)) - 1.0f;
}

__device__ __forceinline__ void mma16816(float* c, u32 a0, u32 a1, u32 a2, u32 a3,
                                         u32 b0, u32 b1) {
    asm volatile("mma.sync.aligned.m16n8k16.row.col.f32.bf16.bf16.f32 "
                 "{%0,%1,%2,%3}, {%4,%5,%6,%7}, {%8,%9}, {%0,%1,%2,%3};"
                 : "+f"(c[0]), "+f"(c[1]), "+f"(c[2]), "+f"(c[3])
                 : "r"(a0), "r"(a1), "r"(a2), "r"(a3), "r"(b0), "r"(b1));
}

// group barrier: 32 blocks sharing bt; monotone generation targets
__device__ __forceinline__ void gbar(unsigned* cnt, unsigned* gen, unsigned target) {
    __syncthreads();
    if (threadIdx.x == 0) {
        unsigned old;
        asm volatile("atom.add.acq_rel.gpu.global.u32 %0, [%1], 1;"
                     : "=r"(old) : "l"(cnt) : "memory");
        if (old == 31u) {
            asm volatile("st.relaxed.gpu.global.u32 [%0], %1;"
                         :: "l"(cnt), "r"(0u) : "memory");
            asm volatile("st.release.gpu.global.u32 [%0], %1;"
                         :: "l"(gen), "r"(target) : "memory");
        } else {
            unsigned v;
            do {
                asm volatile("ld.acquire.gpu.global.u32 %0, [%1];"
                             : "=r"(v) : "l"(gen) : "memory");
            } while (v < target);
        }
    }
    __syncthreads();
}

// ---------------- fused persistent tensor-core LSTM (mma.sync) ----------------
__global__ void __launch_bounds__(TPB, 1)
lstm_mma(const float* __restrict__ x,
         const float* __restrict__ Wgx, const float* __restrict__ Wgh, const float* __restrict__ bg,
         const float* __restrict__ Wix, const float* __restrict__ Wih, const float* __restrict__ bi,
         const float* __restrict__ Wfx, const float* __restrict__ Wfh, const float* __restrict__ bf,
         const float* __restrict__ Wox, const float* __restrict__ Woh, const float* __restrict__ bo,
         const float* __restrict__ Wph, const float* __restrict__ bp,
         float* __restrict__ out) {
    extern __shared__ char smem[];
    float* Dsm = (float*)(smem + SM_D);

    const int tid  = threadIdx.x;
    const int wid  = tid >> 5;
    const int lane = tid & 31;
    const int bt   = blockIdx.x >> 5;     // 0..3 (barrier group, batch slice)
    const int jt   = blockIdx.x & 31;     // 0..31
    const int b0b  = bt * 32;
    const int j0b  = jt * 16;

    unsigned* cnt = &g_cnt4[bt];
    unsigned* gen = &g_gen4[bt];

    // ---- phase 0a: transpose x (group-closed: this bt's b-slice, this jt's t-range) ----
#pragma unroll
    for (int i = 0; i < 2; i++) {
        int idx = tid + i * TPB;              // 0..1023
        int tt  = jt * 32 + (idx >> 5);
        int bb  = b0b + (idx & 31);
        g_xT[tt * B + bb] = x[(size_t)bb * T + tt];
    }

    // ---- phase 0b: pack W tile (bf16 hi/lo) into smem: row n = 4*jl + g ----
    for (int g = 0; g < 4; g++) {
        const float* S = (g == 0) ? Wgh : (g == 1) ? Wih : (g == 2) ? Wfh : Woh;
        for (int i = tid; i < 16 * 512; i += TPB) {
            int jl = i & 15;
            int k  = i >> 4;
            float w = S[k * H + j0b + jl];
            u16 hi = f2bf(w);
            u16 lo = f2bf(w - bf2f(hi));
            int n = jl * 4 + g;
            *(u16*)(smem + SM_BHI + n * RSTRIDE + k * 2) = hi;
            *(u16*)(smem + SM_BLO + n * RSTRIDE + k * 2) = lo;
        }
    }

    // ---- per-thread cell (fixed across time): idx = tid (512 cells) ----
    float wxv[4], bvv[4], cst = 0.f;
    const int cb = tid >> 4;               // 0..31 (batch within slice)
    const int cj = tid & 15;               // 0..15 (j within tile)
    {
        int j = j0b + cj;
        wxv[0] = Wgx[j]; wxv[1] = Wix[j]; wxv[2] = Wfx[j]; wxv[3] = Wox[j];
        bvv[0] = bg[j];  bvv[1] = bi[j];  bvv[2] = bf[j];  bvv[3] = bo[j];
    }

    // ---- warp GEMM coordinates: m32 x n8 tile, k-slice of 256 ----
    const int wn = wid & 7;               // n-tile -> n0 = wn*8
    const int ks = wid >> 3;              // k-slice 0/1 -> k base = ks*256
    const int n0 = wn * 8;
    const int kbase = ks * 512;           // byte offset of k-slice start (256 halves)
    const int aoff = (lane >> 2) * RSTRIDE + (lane & 3) * 4 + kbase;
    const int boff = (n0 + (lane >> 2)) * RSTRIDE + (lane & 3) * 4 + kbase;

    gbar(cnt, gen, 1u);   // x transpose + W pack visible group-wide

    for (int t = 0; t < T; t++) {
        if (t > 0) {
            // ---- stage h hi/lo (32 rows x 512 bf16 each) into padded smem rows ----
            const uint4* shi = g_hhi[t & 1];
            const uint4* slo = g_hlo[t & 1];
#pragma unroll
            for (int i = 0; i < 4; i++) {
                int idx = tid + i * TPB;           // 0..2047
                int r   = idx >> 6;                // 0..31
                int c   = idx & 63;                // uint4 within row
                uint4 vh = __ldcg(shi + ((b0b + r) * H >> 3) + c);
                uint4 vl = __ldcg(slo + ((b0b + r) * H >> 3) + c);
                *(uint4*)(smem + SM_AHI + r * RSTRIDE + c * 16) = vh;
                *(uint4*)(smem + SM_ALO + r * RSTRIDE + c * 16) = vl;
            }
            __syncthreads();

            // ---- fused 3-product GEMM over my k-slice: m32 x n8 ----
            float acc[2][4];               // [mtile][4]
#pragma unroll
            for (int i = 0; i < 2; i++)
#pragma unroll
                for (int q = 0; q < 4; q++) acc[i][q] = 0.f;

            const char* Ah = smem + SM_AHI + aoff;
            const char* Al = smem + SM_ALO + aoff;
            const char* Bh = smem + SM_BHI + boff;
            const char* Bl = smem + SM_BLO + boff;

#pragma unroll 4
            for (int kc = 0; kc < 16; kc++) {
                const int kb = kc * 32;
                u32 ah[2][4], al[2][4];
#pragma unroll
                for (int mtile = 0; mtile < 2; mtile++) {
                    const int mo = mtile * 16 * RSTRIDE;
                    ah[mtile][0] = *(const u32*)(Ah + mo + kb);
                    ah[mtile][1] = *(const u32*)(Ah + mo + 8 * RSTRIDE + kb);
                    ah[mtile][2] = *(const u32*)(Ah + mo + kb + 16);
                    ah[mtile][3] = *(const u32*)(Ah + mo + 8 * RSTRIDE + kb + 16);
                    al[mtile][0] = *(const u32*)(Al + mo + kb);
                    al[mtile][1] = *(const u32*)(Al + mo + 8 * RSTRIDE + kb);
                    al[mtile][2] = *(const u32*)(Al + mo + kb + 16);
                    al[mtile][3] = *(const u32*)(Al + mo + 8 * RSTRIDE + kb + 16);
                }
                u32 bh0 = *(const u32*)(Bh + kb);
                u32 bh1 = *(const u32*)(Bh + kb + 16);
                u32 bl0 = *(const u32*)(Bl + kb);
                u32 bl1 = *(const u32*)(Bl + kb + 16);

#pragma unroll
                for (int mtile = 0; mtile < 2; mtile++) {
                    float* a = acc[mtile];
                    mma16816(a, ah[mtile][0], ah[mtile][1], ah[mtile][2], ah[mtile][3],
                             bh0, bh1);                     // hi * Whi
                    mma16816(a, al[mtile][0], al[mtile][1], al[mtile][2], al[mtile][3],
                             bh0, bh1);                     // lo * Whi
                    mma16816(a, ah[mtile][0], ah[mtile][1], ah[mtile][2], ah[mtile][3],
                             bl0, bl1);                     // hi * Wlo
                }
            }

            // ---- D partial -> smem slice ks (m16n8 fragment layout) ----
            {
                float* Dk = Dsm + ks * (32 * 68);
                const int r  = lane >> 2;
                const int dc = n0 + 2 * (lane & 3);
#pragma unroll
                for (int mtile = 0; mtile < 2; mtile++) {
                    const int dr = mtile * 16 + r;
                    float* a = acc[mtile];
                    *(float2*)(Dk + dr * 68 + dc)       = make_float2(a[0], a[1]);
                    *(float2*)(Dk + (dr + 8) * 68 + dc) = make_float2(a[2], a[3]);
                }
            }
            __syncthreads();
        }

        // ---- epilogue: 1 cell/thread (sum the 2 k-slice partials) ----
        {
            float4 dv;
            if (t > 0) {
                float4 d0 = *(const float4*)(Dsm + cb * 68 + cj * 4);
                float4 d1 = *(const float4*)(Dsm + 32 * 68 + cb * 68 + cj * 4);
                dv = make_float4(d0.x + d1.x, d0.y + d1.y, d0.z + d1.z, d0.w + d1.w);
            } else {
                dv = make_float4(0.f, 0.f, 0.f, 0.f);
            }
            const float xv = g_xT[t * B + b0b + cb];
            float gv = tanf_(dv.x + xv * wxv[0] + bvv[0]);
            float iv = sigf (dv.y + xv * wxv[1] + bvv[1]);
            float fv = sigf (dv.z + xv * wxv[2] + bvv[2]);
            float ov = sigf (dv.w + xv * wxv[3] + bvv[3]);
            cst = gv * iv + cst * fv;
            float hv = tanf_(cst) * ov;
            u16 hi = f2bf(hv);
            u16 lo = f2bf(hv - bf2f(hi));
            const int gidx = (b0b + cb) * H + j0b + cj;
            ((u16*)g_hhi[(t + 1) & 1])[gidx] = hi;
            ((u16*)g_hlo[(t + 1) & 1])[gidx] = lo;
        }

        gbar(cnt, gen, (unsigned)(t + 2));
    }

    // ---- final projection: block handles batch b_out = b0b + jt ----
    {
        const u16* fhi = (const u16*)g_hhi[0];     // T even -> final state in buffer 0
        const u16* flo = (const u16*)g_hlo[0];
        const int b_out = b0b + jt;
        for (int cls = wid; cls < NCLS; cls += 16) {
            const float* wr = Wph + cls * H;
            float s = 0.f;
#pragma unroll
            for (int k = lane; k < H; k += 32) {
                float hv = bf2f(fhi[b_out * H + k]) + bf2f(flo[b_out * H + k]);
                s += hv * wr[k];
            }
#pragma unroll
            for (int off = 16; off; off >>= 1) s += __shfl_down_sync(0xffffffffu, s, off);
            if (lane == 0) out[b_out * NCLS + cls] = s + bp[cls];
        }
    }

    // ---- reset group counters for the next graph replay ----
    __syncthreads();
    if (tid == 0) {
        unsigned old = atomicAdd(cnt, 1u);
        if (old == 31u) {
            asm volatile("st.relaxed.gpu.global.u32 [%0], %1;"
                         :: "l"(cnt), "r"(0u) : "memory");
            asm volatile("st.relaxed.gpu.global.u32 [%0], %1;"
                         :: "l"(gen), "r"(0u) : "memory");
        }
    }
}

// ---------------- launch ----------------
extern "C" void kernel_launch(void* const* d_in, const int* in_sizes, int n_in,
                              void* d_out, int out_size) {
    const float* x   = (const float*)d_in[0];
    const float* Wgx = (const float*)d_in[1];
    const float* Wgh = (const float*)d_in[2];
    const float* bg  = (const float*)d_in[3];
    const float* Wix = (const float*)d_in[4];
    const float* Wih = (const float*)d_in[5];
    const float* bi  = (const float*)d_in[6];
    const float* Wfx = (const float*)d_in[7];
    const float* Wfh = (const float*)d_in[8];
    const float* bf  = (const float*)d_in[9];
    const float* Wox = (const float*)d_in[10];
    const float* Woh = (const float*)d_in[11];
    const float* bo  = (const float*)d_in[12];
    const float* Wph = (const float*)d_in[13];
    const float* bp  = (const float*)d_in[14];
    float* out = (float*)d_out;

    cudaFuncSetAttribute(lstm_mma, cudaFuncAttributeMaxDynamicSharedMemorySize, SMEM_BYTES);

    lstm_mma<<<GRID, TPB, SMEM_BYTES>>>(x,
        Wgx, Wgh, bg, Wix, Wih, bi, Wfx, Wfh, bf, Wox, Woh, bo, Wph, bp, out);
}

// round 17
// speedup vs baseline: 1.1465x; 1.1465x over previous
#include <cuda_runtime.h>

typedef unsigned int   u32;
typedef unsigned short u16;

#define H 512
#define B 128
#define T 1024
#define NCLS 10
#define GRID 128
#define TPB 256

#define RSTRIDE 1040              // bytes per padded A/B smem row (520 halves)
#define SM_AHI 0                  // A hi : 32 rows (Dsm aliases here between GEMM and epilogue)
#define SM_ALO 33280              // A lo : 32 rows
#define SM_BHI 66560              // W hi : 64 rows
#define SM_BLO 133120             // W lo : 64 rows
#define SMEM_BYTES 199680
#define DSLICE 2176               // floats per D k-slice: 32*68

// ---------------- device scratch (static, no allocation) ----------------
__device__ uint4 g_hhi[2][B * H / 8];    // bf16 h hi, [b][k] rows
__device__ uint4 g_hlo[2][B * H / 8];    // bf16 h lo residual
__device__ float g_xT[T * B];            // transposed x [t][b]
__device__ unsigned g_cnt4[4];
__device__ unsigned g_gen4[4];

// ---------------- helpers ----------------
__device__ __forceinline__ u16 f2bf(float f) {
    u32 u = __float_as_uint(f);
    u32 r = (u + 0x7FFFu + ((u >> 16) & 1u)) >> 16;
    return (u16)r;
}
__device__ __forceinline__ float bf2f(u16 s) {
    return __uint_as_float(((u32)s) << 16);
}
__device__ __forceinline__ float sigf(float x) {
    return __fdividef(1.0f, 1.0f + __expf(-x));
}
__device__ __forceinline__ float tanf_(float x) {
    return __fdividef(2.0f, 1.0f + __expf(-2.0f * x)) - 1.0f;
}

__device__ __forceinline__ void mma16816(float* c, u32 a0, u32 a1, u32 a2, u32 a3,
                                         u32 b0, u32 b1) {
    asm volatile("mma.sync.aligned.m16n8k16.row.col.f32.bf16.bf16.f32 "
                 "{%0,%1,%2,%3}, {%4,%5,%6,%7}, {%8,%9}, {%0,%1,%2,%3};"
                 : "+f"(c[0]), "+f"(c[1]), "+f"(c[2]), "+f"(c[3])
                 : "r"(a0), "r"(a1), "r"(a2), "r"(a3), "r"(b0), "r"(b1));
}

// group barrier: 32 blocks sharing bt; monotone generation targets
__device__ __forceinline__ void gbar(unsigned* cnt, unsigned* gen, unsigned target) {
    __syncthreads();
    if (threadIdx.x == 0) {
        unsigned old;
        asm volatile("atom.add.acq_rel.gpu.global.u32 %0, [%1], 1;"
                     : "=r"(old) : "l"(cnt) : "memory");
        if (old == 31u) {
            asm volatile("st.relaxed.gpu.global.u32 [%0], %1;"
                         :: "l"(cnt), "r"(0u) : "memory");
            asm volatile("st.release.gpu.global.u32 [%0], %1;"
                         :: "l"(gen), "r"(target) : "memory");
        } else {
            unsigned v;
            do {
                asm volatile("ld.acquire.gpu.global.u32 %0, [%1];"
                             : "=r"(v) : "l"(gen) : "memory");
            } while (v < target);
        }
    }
    __syncthreads();
}

// ---------------- fused persistent tensor-core LSTM (mma.sync) ----------------
__global__ void __launch_bounds__(TPB, 1)
lstm_mma(const float* __restrict__ x,
         const float* __restrict__ Wgx, const float* __restrict__ Wgh, const float* __restrict__ bg,
         const float* __restrict__ Wix, const float* __restrict__ Wih, const float* __restrict__ bi,
         const float* __restrict__ Wfx, const float* __restrict__ Wfh, const float* __restrict__ bf,
         const float* __restrict__ Wox, const float* __restrict__ Woh, const float* __restrict__ bo,
         const float* __restrict__ Wph, const float* __restrict__ bp,
         float* __restrict__ out) {
    extern __shared__ char smem[];
    float* Dsm = (float*)(smem + SM_AHI);   // aliases A region (A dead when D is written)

    const int tid  = threadIdx.x;
    const int wid  = tid >> 5;
    const int lane = tid & 31;
    const int bt   = blockIdx.x >> 5;     // 0..3 (barrier group, batch slice)
    const int jt   = blockIdx.x & 31;     // 0..31
    const int b0b  = bt * 32;
    const int j0b  = jt * 16;

    unsigned* cnt = &g_cnt4[bt];
    unsigned* gen = &g_gen4[bt];

    // ---- phase 0a: transpose x (group-closed: this bt's b-slice, this jt's t-range) ----
#pragma unroll
    for (int i = 0; i < 4; i++) {
        int idx = tid + i * TPB;              // 0..1023
        int tt  = jt * 32 + (idx >> 5);
        int bb  = b0b + (idx & 31);
        g_xT[tt * B + bb] = x[(size_t)bb * T + tt];
    }

    // ---- phase 0b: pack W tile (bf16 hi/lo) into smem: row n = 4*jl + g ----
    for (int g = 0; g < 4; g++) {
        const float* S = (g == 0) ? Wgh : (g == 1) ? Wih : (g == 2) ? Wfh : Woh;
        for (int i = tid; i < 16 * 512; i += TPB) {
            int jl = i & 15;
            int k  = i >> 4;
            float w = S[k * H + j0b + jl];
            u16 hi = f2bf(w);
            u16 lo = f2bf(w - bf2f(hi));
            int n = jl * 4 + g;
            *(u16*)(smem + SM_BHI + n * RSTRIDE + k * 2) = hi;
            *(u16*)(smem + SM_BLO + n * RSTRIDE + k * 2) = lo;
        }
    }

    // ---- per-thread cells (fixed across time): idx = tid, tid+256 ----
    float wx[2][4], bv[2][4], cst[2];
    int cb[2], cj[2];
#pragma unroll
    for (int ci = 0; ci < 2; ci++) {
        int idx = tid + ci * 256;
        cb[ci] = idx >> 4;                 // 0..31 (batch within slice)
        cj[ci] = idx & 15;                 // 0..15 (j within tile)
        int j = j0b + cj[ci];
        wx[ci][0] = Wgx[j]; wx[ci][1] = Wix[j]; wx[ci][2] = Wfx[j]; wx[ci][3] = Wox[j];
        bv[ci][0] = bg[j];  bv[ci][1] = bi[j];  bv[ci][2] = bf[j];  bv[ci][3] = bo[j];
        cst[ci] = 0.f;
    }

    // ---- warp GEMM coordinates: m32 x n32 tile, k-slice of 128 ----
    const int wn = wid & 1;               // n-tile -> n0 = wn*32
    const int ks = wid >> 1;              // k-slice 0..3 -> k base = ks*128
    const int n0 = wn * 32;
    const int kbase = ks * 256;           // byte offset of k-slice start (128 halves)
    const int aoff = (lane >> 2) * RSTRIDE + (lane & 3) * 4 + kbase;
    const int boff = (n0 + (lane >> 2)) * RSTRIDE + (lane & 3) * 4 + kbase;

    gbar(cnt, gen, 1u);   // x transpose + W pack visible group-wide

    for (int t = 0; t < T; t++) {
        if (t > 0) {
            // ---- stage h hi/lo (32 rows x 512 bf16 each) into padded smem rows ----
            const uint4* shi = g_hhi[t & 1];
            const uint4* slo = g_hlo[t & 1];
#pragma unroll
            for (int i = 0; i < 8; i++) {
                int idx = tid + i * TPB;           // 0..2047
                int r   = idx >> 6;                // 0..31
                int c   = idx & 63;                // uint4 within row
                uint4 vh = __ldcg(shi + ((b0b + r) * H >> 3) + c);
                uint4 vl = __ldcg(slo + ((b0b + r) * H >> 3) + c);
                *(uint4*)(smem + SM_AHI + r * RSTRIDE + c * 16) = vh;
                *(uint4*)(smem + SM_ALO + r * RSTRIDE + c * 16) = vl;
            }
            __syncthreads();

            // ---- fused 3-product GEMM over my k-slice: m32 x n32 ----
            float acc[8][4];               // [mtile*4 + nblk][4]
#pragma unroll
            for (int i = 0; i < 8; i++)
#pragma unroll
                for (int q = 0; q < 4; q++) acc[i][q] = 0.f;

            const char* Ah = smem + SM_AHI + aoff;
            const char* Al = smem + SM_ALO + aoff;
            const char* Bh = smem + SM_BHI + boff;
            const char* Bl = smem + SM_BLO + boff;

#pragma unroll 2
            for (int kc = 0; kc < 8; kc++) {
                const int kb = kc * 32;
                u32 ah[2][4], al[2][4];
#pragma unroll
                for (int mtile = 0; mtile < 2; mtile++) {
                    const int mo = mtile * 16 * RSTRIDE;
                    ah[mtile][0] = *(const u32*)(Ah + mo + kb);
                    ah[mtile][1] = *(const u32*)(Ah + mo + 8 * RSTRIDE + kb);
                    ah[mtile][2] = *(const u32*)(Ah + mo + kb + 16);
                    ah[mtile][3] = *(const u32*)(Ah + mo + 8 * RSTRIDE + kb + 16);
                    al[mtile][0] = *(const u32*)(Al + mo + kb);
                    al[mtile][1] = *(const u32*)(Al + mo + 8 * RSTRIDE + kb);
                    al[mtile][2] = *(const u32*)(Al + mo + kb + 16);
                    al[mtile][3] = *(const u32*)(Al + mo + 8 * RSTRIDE + kb + 16);
                }
                u32 bh[4][2], bl[4][2];
#pragma unroll
                for (int nb = 0; nb < 4; nb++) {
                    const int no = nb * 8 * RSTRIDE;
                    bh[nb][0] = *(const u32*)(Bh + no + kb);
                    bh[nb][1] = *(const u32*)(Bh + no + kb + 16);
                    bl[nb][0] = *(const u32*)(Bl + no + kb);
                    bl[nb][1] = *(const u32*)(Bl + no + kb + 16);
                }

#pragma unroll
                for (int mtile = 0; mtile < 2; mtile++) {
#pragma unroll
                    for (int nb = 0; nb < 4; nb++) {
                        float* a = acc[mtile * 4 + nb];
                        mma16816(a, ah[mtile][0], ah[mtile][1], ah[mtile][2], ah[mtile][3],
                                 bh[nb][0], bh[nb][1]);                     // hi * Whi
                        mma16816(a, al[mtile][0], al[mtile][1], al[mtile][2], al[mtile][3],
                                 bh[nb][0], bh[nb][1]);                     // lo * Whi
                        mma16816(a, ah[mtile][0], ah[mtile][1], ah[mtile][2], ah[mtile][3],
                                 bl[nb][0], bl[nb][1]);                     // hi * Wlo
                    }
                }
            }

            // ---- all warps done reading A before D overwrites the A region ----
            __syncthreads();

            // ---- D partial -> Dsm slice ks (m16n8 fragment layout, aliases A) ----
            {
                float* Dk = Dsm + ks * DSLICE;
                const int r  = lane >> 2;
                const int dc = n0 + 2 * (lane & 3);
#pragma unroll
                for (int mtile = 0; mtile < 2; mtile++) {
                    const int dr = mtile * 16 + r;
#pragma unroll
                    for (int nb = 0; nb < 4; nb++) {
                        float* a = acc[mtile * 4 + nb];
                        *(float2*)(Dk + dr * 68 + dc + nb * 8)       = make_float2(a[0], a[1]);
                        *(float2*)(Dk + (dr + 8) * 68 + dc + nb * 8) = make_float2(a[2], a[3]);
                    }
                }
            }
            __syncthreads();
        }

        // ---- epilogue: 2 cells/thread (sum the 4 k-slice partials) ----
        u16* whi = (u16*)g_hhi[(t + 1) & 1];
        u16* wlo = (u16*)g_hlo[(t + 1) & 1];
#pragma unroll
        for (int ci = 0; ci < 2; ci++) {
            float4 dv = make_float4(0.f, 0.f, 0.f, 0.f);
            if (t > 0) {
#pragma unroll
                for (int p = 0; p < 4; p++) {
                    float4 d = *(const float4*)(Dsm + p * DSLICE + cb[ci] * 68 + cj[ci] * 4);
                    dv.x += d.x; dv.y += d.y; dv.z += d.z; dv.w += d.w;
                }
            }
            const float xv = g_xT[t * B + b0b + cb[ci]];
            float gv = tanf_(dv.x + xv * wx[ci][0] + bv[ci][0]);
            float iv = sigf (dv.y + xv * wx[ci][1] + bv[ci][1]);
            float fv = sigf (dv.z + xv * wx[ci][2] + bv[ci][2]);
            float ov = sigf (dv.w + xv * wx[ci][3] + bv[ci][3]);
            cst[ci] = gv * iv + cst[ci] * fv;
            float hv = tanf_(cst[ci]) * ov;
            u16 hi = f2bf(hv);
            u16 lo = f2bf(hv - bf2f(hi));
            const int gidx = (b0b + cb[ci]) * H + j0b + cj[ci];
            whi[gidx] = hi;
            wlo[gidx] = lo;
        }

        gbar(cnt, gen, (unsigned)(t + 2));
    }

    // ---- final projection: block handles batch b_out = b0b + jt ----
    {
        const u16* fhi = (const u16*)g_hhi[0];     // T even -> final state in buffer 0
        const u16* flo = (const u16*)g_hlo[0];
        const int b_out = b0b + jt;
        for (int cls = wid; cls < NCLS; cls += 8) {
            const float* wr = Wph + cls * H;
            float s = 0.f;
#pragma unroll
            for (int k = lane; k < H; k += 32) {
                float hv = bf2f(fhi[b_out * H + k]) + bf2f(flo[b_out * H + k]);
                s += hv * wr[k];
            }
#pragma unroll
            for (int off = 16; off; off >>= 1) s += __shfl_down_sync(0xffffffffu, s, off);
            if (lane == 0) out[b_out * NCLS + cls] = s + bp[cls];
        }
    }

    // ---- reset group counters for the next graph replay ----
    __syncthreads();
    if (tid == 0) {
        unsigned old = atomicAdd(cnt, 1u);
        if (old == 31u) {
            asm volatile("st.relaxed.gpu.global.u32 [%0], %1;"
                         :: "l"(cnt), "r"(0u) : "memory");
            asm volatile("st.relaxed.gpu.global.u32 [%0], %1;"
                         :: "l"(gen), "r"(0u) : "memory");
        }
    }
}

// ---------------- launch ----------------
extern "C" void kernel_launch(void* const* d_in, const int* in_sizes, int n_in,
                              void* d_out, int out_size) {
    const float* x   = (const float*)d_in[0];
    const float* Wgx = (const float*)d_in[1];
    const float* Wgh = (const float*)d_in[2];
    const float* bg  = (const float*)d_in[3];
    const float* Wix = (const float*)d_in[4];
    const float* Wih = (const float*)d_in[5];
    const float* bi  = (const float*)d_in[6];
    const float* Wfx = (const float*)d_in[7];
    const float* Wfh = (const float*)d_in[8];
    const float* bf  = (const float*)d_in[9];
    const float* Wox = (const float*)d_in[10];
    const float* Woh = (const float*)d_in[11];
    const float* bo  = (const float*)d_in[12];
    const float* Wph = (const float*)d_in[13];
    const float* bp  = (const float*)d_in[14];
    float* out = (float*)d_out;

    cudaFuncSetAttribute(lstm_mma, cudaFuncAttributeMaxDynamicSharedMemorySize, SMEM_BYTES);

    lstm_mma<<<GRID, TPB, SMEM_BYTES>>>(x,
        Wgx, Wgh, bg, Wix, Wih, bi, Wfx, Wfh, bf, Wox, Woh, bo, Wph, bp, out);
}